// round 4
// baseline (speedup 1.0000x reference)
#include <cuda_runtime.h>

#define FULLMASK 0xffffffffu
#define WSTRIDE 258
#define NTHREADS 512
#define JB 4                            // batches per thread

// ---- smem layout (float offsets) ----
#define OFF_W1T  0                      // [64][258]  Whh1^T
#define OFF_W2T  (64 * WSTRIDE)         // [128][258] rows 0..63 Wih2^T, 64..127 Whh2^T
#define OFF_WIH1 (OFF_W2T + 128 * WSTRIDE)
#define OFF_CB1  (OFF_WIH1 + 256)
#define OFF_CB2  (OFF_CB1 + 256)
#define OFF_WOUT (OFF_CB2 + 256)        // [2][1664]
#define OFF_XS   (OFF_WOUT + 3328)      // [64][24]
#define SMEM_FLOATS (OFF_XS + 64 * 24)
#define SMEM_BYTES  (SMEM_FLOATS * 4)   // 220672 B

typedef unsigned long long u64;

static __device__ __forceinline__ u64 splat2(float x) {
    u64 d;
    asm("mov.b64 %0, {%1, %1};" : "=l"(d) : "f"(x));
    return d;
}
static __device__ __forceinline__ float2 unpack2(u64 v) {
    float lo, hi;
    asm("mov.b64 {%0, %1}, %2;" : "=f"(lo), "=f"(hi) : "l"(v));
    return make_float2(lo, hi);
}
static __device__ __forceinline__ u64 fma2(u64 a, u64 b, u64 c) {
    u64 d;
    asm("fma.rn.f32x2 %0, %1, %2, %3;" : "=l"(d) : "l"(a), "l"(b), "l"(c));
    return d;
}

// Fused SLSTM pointwise with shared reciprocals: 5 EX2 + 2 RCP (vs 10 MUFU).
// syn' = [a*b*syn + c*(2-b)] / (a*b*c);  a=1+e^-i, b=1+e^-2g, c=1+e^-f
// mem' = (2-q)/(p*q) - reset;            p=1+e^-o, q=1+e^-2*syn'
static __device__ __forceinline__ void cellpw(float Gi, float Gf, float Gg, float Go,
                                              float& syn, float& mem, float& spk,
                                              float thr) {
    float a = 1.0f + __expf(-Gi);
    float c = 1.0f + __expf(-Gf);
    float b = 1.0f + __expf(-2.0f * Gg);
    float ab = a * b;
    float r = __fdividef(1.0f, ab * c);
    float sn = (ab * syn + c * (2.0f - b)) * r;
    float p = 1.0f + __expf(-Go);
    float q = 1.0f + __expf(-2.0f * sn);
    float s = __fdividef(1.0f, p * q);
    float rst = (mem > thr) ? thr : 0.0f;
    float mn = s * (2.0f - q) - rst;
    syn = sn;
    mem = mn;
    spk = (mn > thr) ? 1.0f : 0.0f;
}

// 64-row matvec: acc[g][j] (f32x2 over neuron pair n0,n0+1) +=
// src[h] * W[h][g*64 + n0..n0+1]; src broadcast from owning lane via shfl.
static __device__ __forceinline__ void gemm64(u64 (&acc)[4][JB],
                                              const float* __restrict__ wbase,
                                              const float (&src)[2][JB], int n0) {
#pragma unroll 4
    for (int h2 = 0; h2 < 32; ++h2) {
        const float* wr = wbase + (h2 * 2) * WSTRIDE;
        u64 w2a[4], w2b[4];
#pragma unroll
        for (int g = 0; g < 4; ++g) {
            w2a[g] = *(const u64*)(wr + g * 64 + n0);
            w2b[g] = *(const u64*)(wr + WSTRIDE + g * 64 + n0);
        }
#pragma unroll
        for (int j = 0; j < JB; ++j) {
            u64 sa = splat2(__shfl_sync(FULLMASK, src[0][j], h2));
#pragma unroll
            for (int g = 0; g < 4; ++g) acc[g][j] = fma2(sa, w2a[g], acc[g][j]);
        }
#pragma unroll
        for (int j = 0; j < JB; ++j) {
            u64 sb = splat2(__shfl_sync(FULLMASK, src[1][j], h2));
#pragma unroll
            for (int g = 0; g < 4; ++g) acc[g][j] = fma2(sb, w2b[g], acc[g][j]);
        }
    }
}

__global__ void __launch_bounds__(NTHREADS, 1)
snn_kernel(const float* __restrict__ x,
           const float* __restrict__ Wih1, const float* __restrict__ Whh1,
           const float* __restrict__ bih1, const float* __restrict__ bhh1,
           const float* __restrict__ thr1p,
           const float* __restrict__ Wih2, const float* __restrict__ Whh2,
           const float* __restrict__ bih2, const float* __restrict__ bhh2,
           const float* __restrict__ thr2p,
           const float* __restrict__ Wout, const float* __restrict__ bout,
           float* __restrict__ out) {
    extern __shared__ float sm[];
    const int tid  = threadIdx.x;
    const int lane = tid & 31;
    const int w    = tid >> 5;
    const int n0   = lane << 1;          // this lane's neuron pair
    const int bl   = w * JB;             // local batch base (JB per warp)
    const int cta_b0 = blockIdx.x * 64;

    // ---- stage weights (transposed, stride 258 -> conflict-free reads) ----
    for (int i = tid; i < 256 * 64; i += NTHREADS) {
        int r = i >> 6, h = i & 63;
        sm[OFF_W1T + h * WSTRIDE + r]        = Whh1[i];
        sm[OFF_W2T + h * WSTRIDE + r]        = Wih2[i];
        sm[OFF_W2T + (64 + h) * WSTRIDE + r] = Whh2[i];
    }
    if (tid < 256) {
        sm[OFF_WIH1 + tid] = Wih1[tid];
        sm[OFF_CB1 + tid]  = bih1[tid] + bhh1[tid];
        sm[OFF_CB2 + tid]  = bih2[tid] + bhh2[tid];
    }
    for (int i = tid; i < 3328; i += NTHREADS) sm[OFF_WOUT + i] = Wout[i];
    for (int i = tid; i < 64 * 24; i += NTHREADS) sm[OFF_XS + i] = x[cta_b0 * 24 + i];
    __syncthreads();

    const float thr1 = thr1p[0], thr2 = thr2p[0];

    // register-resident state: [neuron 0/1][batch j]
    float syn1[2][JB], mem1[2][JB], syn2[2][JB], mem2[2][JB], spk1[2][JB];
#pragma unroll
    for (int n = 0; n < 2; ++n)
#pragma unroll
        for (int j = 0; j < JB; ++j)
            syn1[n][j] = mem1[n][j] = syn2[n][j] = mem2[n][j] = spk1[n][j] = 0.0f;

    float oa[JB][2];
#pragma unroll
    for (int j = 0; j < JB; ++j) oa[j][0] = oa[j][1] = 0.0f;

    u64 acc[4][JB];

#pragma unroll 1
    for (int t = 0; t < 25; ++t) {
        if (t < 24) {
            // ---- layer 1: gates = mem1 @ Whh1^T + x*Wih1 + b ----
#pragma unroll
            for (int g = 0; g < 4; ++g)
#pragma unroll
                for (int j = 0; j < JB; ++j) acc[g][j] = 0ull;
            gemm64(acc, sm + OFF_W1T, mem1, n0);
#pragma unroll
            for (int j = 0; j < JB; ++j) {
                float xv = sm[OFF_XS + (bl + j) * 24 + t];
                float2 gi = unpack2(acc[0][j]);
                float2 gf = unpack2(acc[1][j]);
                float2 gg = unpack2(acc[2][j]);
                float2 go = unpack2(acc[3][j]);
#pragma unroll
                for (int n = 0; n < 2; ++n) {
                    float Gi = (n ? gi.y : gi.x) + sm[OFF_CB1 + 0 * 64 + n0 + n]
                             + xv * sm[OFF_WIH1 + 0 * 64 + n0 + n];
                    float Gf = (n ? gf.y : gf.x) + sm[OFF_CB1 + 1 * 64 + n0 + n]
                             + xv * sm[OFF_WIH1 + 1 * 64 + n0 + n];
                    float Gg = (n ? gg.y : gg.x) + sm[OFF_CB1 + 2 * 64 + n0 + n]
                             + xv * sm[OFF_WIH1 + 2 * 64 + n0 + n];
                    float Go = (n ? go.y : go.x) + sm[OFF_CB1 + 3 * 64 + n0 + n]
                             + xv * sm[OFF_WIH1 + 3 * 64 + n0 + n];
                    cellpw(Gi, Gf, Gg, Go, syn1[n][j], mem1[n][j], spk1[n][j], thr1);
                }
            }
        }
        // ---- layer 2: input = spk1 (t<24) or mem1 (extra step t==24) ----
#pragma unroll
        for (int g = 0; g < 4; ++g)
#pragma unroll
            for (int j = 0; j < JB; ++j) acc[g][j] = 0ull;
        gemm64(acc, sm + OFF_W2T + 64 * WSTRIDE, mem2, n0);
        if (t < 24) gemm64(acc, sm + OFF_W2T, spk1, n0);
        else        gemm64(acc, sm + OFF_W2T, mem1, n0);

        const int wcol = t * 64;
#pragma unroll
        for (int j = 0; j < JB; ++j) {
            float2 gi = unpack2(acc[0][j]);
            float2 gf = unpack2(acc[1][j]);
            float2 gg = unpack2(acc[2][j]);
            float2 go = unpack2(acc[3][j]);
#pragma unroll
            for (int n = 0; n < 2; ++n) {
                float Gi = (n ? gi.y : gi.x) + sm[OFF_CB2 + 0 * 64 + n0 + n];
                float Gf = (n ? gf.y : gf.x) + sm[OFF_CB2 + 1 * 64 + n0 + n];
                float Gg = (n ? gg.y : gg.x) + sm[OFF_CB2 + 2 * 64 + n0 + n];
                float Go = (n ? go.y : go.x) + sm[OFF_CB2 + 3 * 64 + n0 + n];
                float sp;
                cellpw(Gi, Gf, Gg, Go, syn2[n][j], mem2[n][j], sp, thr2);
                oa[j][0] += sp * sm[OFF_WOUT + wcol + n0 + n];
                oa[j][1] += sp * sm[OFF_WOUT + 1664 + wcol + n0 + n];
            }
        }
    }

    // ---- final mem2 contribution (columns 25*64 .. 25*64+63) ----
#pragma unroll
    for (int n = 0; n < 2; ++n) {
        float wm0 = sm[OFF_WOUT + 25 * 64 + n0 + n];
        float wm1 = sm[OFF_WOUT + 1664 + 25 * 64 + n0 + n];
#pragma unroll
        for (int j = 0; j < JB; ++j) {
            oa[j][0] += mem2[n][j] * wm0;
            oa[j][1] += mem2[n][j] * wm1;
        }
    }

    // ---- warp reduction over the 32 neuron-owner lanes ----
#pragma unroll
    for (int j = 0; j < JB; ++j)
#pragma unroll
        for (int k = 0; k < 2; ++k) {
            float v = oa[j][k];
#pragma unroll
            for (int off = 16; off; off >>= 1)
                v += __shfl_xor_sync(FULLMASK, v, off);
            oa[j][k] = v;
        }

    if (lane < 2 * JB) {
        int j = lane >> 1, k = lane & 1;
        out[(cta_b0 + bl + j) * 2 + k] = oa[j][k] + bout[k];
    }
}

extern "C" void kernel_launch(void* const* d_in, const int* in_sizes, int n_in,
                              void* d_out, int out_size) {
    const float* x    = (const float*)d_in[0];
    const float* Wih1 = (const float*)d_in[1];
    const float* Whh1 = (const float*)d_in[2];
    const float* bih1 = (const float*)d_in[3];
    const float* bhh1 = (const float*)d_in[4];
    const float* thr1 = (const float*)d_in[5];
    const float* Wih2 = (const float*)d_in[6];
    const float* Whh2 = (const float*)d_in[7];
    const float* bih2 = (const float*)d_in[8];
    const float* bhh2 = (const float*)d_in[9];
    const float* thr2 = (const float*)d_in[10];
    const float* Wout = (const float*)d_in[11];
    const float* bout = (const float*)d_in[12];
    float* out = (float*)d_out;

    int B = in_sizes[0] / 24;  // 65536

    cudaFuncSetAttribute(snn_kernel,
                         cudaFuncAttributeMaxDynamicSharedMemorySize,
                         SMEM_BYTES);

    snn_kernel<<<B / 64, NTHREADS, SMEM_BYTES>>>(
        x, Wih1, Whh1, bih1, bhh1, thr1,
        Wih2, Whh2, bih2, bhh2, thr2, Wout, bout, out);
}

// round 5
// speedup vs baseline: 1.0789x; 1.0789x over previous
#include <cuda_runtime.h>

#define FULLMASK 0xffffffffu
#define WSTRIDE 260
#define NT 256
#define JB 4                            // batches per thread (half-warp split)

// ---- smem layout (float offsets) ----
#define OFF_W1T  0                      // [64][260]  Whh1^T
#define OFF_W2T  (64 * WSTRIDE)         // [128][260] rows 0..63 Wih2^T, 64..127 Whh2^T
#define OFF_WIH1 (OFF_W2T + 128 * WSTRIDE)
#define OFF_CB1  (OFF_WIH1 + 256)
#define OFF_CB2  (OFF_CB1 + 256)
#define OFF_WOUT (OFF_CB2 + 256)        // [2][1664]
#define OFF_XS   (OFF_WOUT + 3328)      // [64][24]
#define SMEM_FLOATS (OFF_XS + 64 * 24)
#define SMEM_BYTES  (SMEM_FLOATS * 4)   // 222208 B

typedef unsigned long long u64;

static __device__ __forceinline__ u64 splat2(float x) {
    u64 d;
    asm("mov.b64 %0, {%1, %1};" : "=l"(d) : "f"(x));
    return d;
}
static __device__ __forceinline__ float2 unpack2(u64 v) {
    float lo, hi;
    asm("mov.b64 {%0, %1}, %2;" : "=f"(lo), "=f"(hi) : "l"(v));
    return make_float2(lo, hi);
}
static __device__ __forceinline__ u64 fma2(u64 a, u64 b, u64 c) {
    u64 d;
    asm("fma.rn.f32x2 %0, %1, %2, %3;" : "=l"(d) : "l"(a), "l"(b), "l"(c));
    return d;
}

// Fused SLSTM pointwise with shared reciprocals: 5 EX2 + 2 RCP.
// syn' = [a*b*syn + c*(2-b)] / (a*b*c);  a=1+e^-i, b=1+e^-2g, c=1+e^-f
// mem' = (2-q)/(p*q) - reset;            p=1+e^-o, q=1+e^-2*syn'
static __device__ __forceinline__ void cellpw(float Gi, float Gf, float Gg, float Go,
                                              float& syn, float& mem, float& spk,
                                              float thr) {
    float a = 1.0f + __expf(-Gi);
    float c = 1.0f + __expf(-Gf);
    float b = 1.0f + __expf(-2.0f * Gg);
    float ab = a * b;
    float r = __fdividef(1.0f, ab * c);
    float sn = (ab * syn + c * (2.0f - b)) * r;
    float p = 1.0f + __expf(-Go);
    float q = 1.0f + __expf(-2.0f * sn);
    float s = __fdividef(1.0f, p * q);
    float rst = (mem > thr) ? thr : 0.0f;
    float mn = s * (2.0f - q) - rst;
    syn = sn;
    mem = mn;
    spk = (mn > thr) ? 1.0f : 0.0f;
}

// 64-row matvec. Lane owns neurons n0..n0+3 (n0 = 4*(lane&15)); lanes >=16
// handle the other 4 batches. src[n][j] = state of neuron 4*(lane&15)+n for
// batch j of this half-warp. Broadcast via shfl from owning lane (srcbase+h4).
// acc[g][j][p]: f32x2 over neurons n0+2p, n0+2p+1.
static __device__ __forceinline__ void gemm64(u64 (&acc)[4][JB][2],
                                              const float* __restrict__ wbase,
                                              const float (&src)[4][JB],
                                              int srcbase, int n0) {
#pragma unroll 2
    for (int h4 = 0; h4 < 16; ++h4) {
#pragma unroll
        for (int n = 0; n < 4; ++n) {
            const float* wr = wbase + (h4 * 4 + n) * WSTRIDE + n0;
            ulonglong2 wg0 = *(const ulonglong2*)(wr);
            ulonglong2 wg1 = *(const ulonglong2*)(wr + 64);
            ulonglong2 wg2 = *(const ulonglong2*)(wr + 128);
            ulonglong2 wg3 = *(const ulonglong2*)(wr + 192);
#pragma unroll
            for (int j = 0; j < JB; ++j) {
                u64 s = splat2(__shfl_sync(FULLMASK, src[n][j], srcbase + h4));
                acc[0][j][0] = fma2(s, wg0.x, acc[0][j][0]);
                acc[0][j][1] = fma2(s, wg0.y, acc[0][j][1]);
                acc[1][j][0] = fma2(s, wg1.x, acc[1][j][0]);
                acc[1][j][1] = fma2(s, wg1.y, acc[1][j][1]);
                acc[2][j][0] = fma2(s, wg2.x, acc[2][j][0]);
                acc[2][j][1] = fma2(s, wg2.y, acc[2][j][1]);
                acc[3][j][0] = fma2(s, wg3.x, acc[3][j][0]);
                acc[3][j][1] = fma2(s, wg3.y, acc[3][j][1]);
            }
        }
    }
}

__global__ void __launch_bounds__(NT, 1)
snn_kernel(const float* __restrict__ x,
           const float* __restrict__ Wih1, const float* __restrict__ Whh1,
           const float* __restrict__ bih1, const float* __restrict__ bhh1,
           const float* __restrict__ thr1p,
           const float* __restrict__ Wih2, const float* __restrict__ Whh2,
           const float* __restrict__ bih2, const float* __restrict__ bhh2,
           const float* __restrict__ thr2p,
           const float* __restrict__ Wout, const float* __restrict__ bout,
           float* __restrict__ out) {
    extern __shared__ float sm[];
    const int tid  = threadIdx.x;
    const int lane = tid & 31;
    const int w    = tid >> 5;
    const int hl   = lane & 15;          // position within half-warp
    const int bg   = lane >> 4;          // batch group (0/1)
    const int n0   = hl << 2;            // this lane's 4 neurons
    const int srcbase = bg << 4;
    const int bl   = w * 8 + bg * JB;    // local batch base (JB per half-warp)
    const int cta_b0 = blockIdx.x * 64;

    // ---- stage weights (transposed, stride 260: LDS.128-aligned) ----
    for (int i = tid; i < 256 * 64; i += NT) {
        int r = i >> 6, h = i & 63;
        sm[OFF_W1T + h * WSTRIDE + r]        = Whh1[i];
        sm[OFF_W2T + h * WSTRIDE + r]        = Wih2[i];
        sm[OFF_W2T + (64 + h) * WSTRIDE + r] = Whh2[i];
    }
    if (tid < 256) {
        sm[OFF_WIH1 + tid] = Wih1[tid];
        sm[OFF_CB1 + tid]  = bih1[tid] + bhh1[tid];
        sm[OFF_CB2 + tid]  = bih2[tid] + bhh2[tid];
    }
    for (int i = tid; i < 3328; i += NT) sm[OFF_WOUT + i] = Wout[i];
    for (int i = tid; i < 64 * 24; i += NT) sm[OFF_XS + i] = x[cta_b0 * 24 + i];
    __syncthreads();

    const float thr1 = thr1p[0], thr2 = thr2p[0];

    // register-resident state: [neuron component 0..3][batch j]
    float syn1[4][JB], mem1[4][JB], syn2[4][JB], mem2[4][JB], spk1[4][JB];
#pragma unroll
    for (int n = 0; n < 4; ++n)
#pragma unroll
        for (int j = 0; j < JB; ++j)
            syn1[n][j] = mem1[n][j] = syn2[n][j] = mem2[n][j] = spk1[n][j] = 0.0f;

    float oa[JB][2];
#pragma unroll
    for (int j = 0; j < JB; ++j) oa[j][0] = oa[j][1] = 0.0f;

    u64 acc[4][JB][2];

#pragma unroll 1
    for (int t = 0; t < 25; ++t) {
        if (t < 24) {
            // ---- layer 1: gates = mem1 @ Whh1^T + x*Wih1 + b ----
#pragma unroll
            for (int g = 0; g < 4; ++g)
#pragma unroll
                for (int j = 0; j < JB; ++j) acc[g][j][0] = acc[g][j][1] = 0ull;
            gemm64(acc, sm + OFF_W1T, mem1, srcbase, n0);
#pragma unroll
            for (int j = 0; j < JB; ++j) {
                float xv = sm[OFF_XS + (bl + j) * 24 + t];
                float2 G[4][2];
#pragma unroll
                for (int g = 0; g < 4; ++g) {
                    G[g][0] = unpack2(acc[g][j][0]);
                    G[g][1] = unpack2(acc[g][j][1]);
                }
#pragma unroll
                for (int n = 0; n < 4; ++n) {
                    float Gi = ((n & 1) ? G[0][n >> 1].y : G[0][n >> 1].x)
                             + sm[OFF_CB1 + 0 * 64 + n0 + n]
                             + xv * sm[OFF_WIH1 + 0 * 64 + n0 + n];
                    float Gf = ((n & 1) ? G[1][n >> 1].y : G[1][n >> 1].x)
                             + sm[OFF_CB1 + 1 * 64 + n0 + n]
                             + xv * sm[OFF_WIH1 + 1 * 64 + n0 + n];
                    float Gg = ((n & 1) ? G[2][n >> 1].y : G[2][n >> 1].x)
                             + sm[OFF_CB1 + 2 * 64 + n0 + n]
                             + xv * sm[OFF_WIH1 + 2 * 64 + n0 + n];
                    float Go = ((n & 1) ? G[3][n >> 1].y : G[3][n >> 1].x)
                             + sm[OFF_CB1 + 3 * 64 + n0 + n]
                             + xv * sm[OFF_WIH1 + 3 * 64 + n0 + n];
                    cellpw(Gi, Gf, Gg, Go, syn1[n][j], mem1[n][j], spk1[n][j], thr1);
                }
            }
        }
        // ---- layer 2: input = spk1 (t<24) or mem1 (extra step t==24) ----
#pragma unroll
        for (int g = 0; g < 4; ++g)
#pragma unroll
            for (int j = 0; j < JB; ++j) acc[g][j][0] = acc[g][j][1] = 0ull;
        gemm64(acc, sm + OFF_W2T + 64 * WSTRIDE, mem2, srcbase, n0);
        if (t < 24) gemm64(acc, sm + OFF_W2T, spk1, srcbase, n0);
        else        gemm64(acc, sm + OFF_W2T, mem1, srcbase, n0);

        const int wcol = t * 64;
#pragma unroll
        for (int j = 0; j < JB; ++j) {
            float2 G[4][2];
#pragma unroll
            for (int g = 0; g < 4; ++g) {
                G[g][0] = unpack2(acc[g][j][0]);
                G[g][1] = unpack2(acc[g][j][1]);
            }
#pragma unroll
            for (int n = 0; n < 4; ++n) {
                float Gi = ((n & 1) ? G[0][n >> 1].y : G[0][n >> 1].x)
                         + sm[OFF_CB2 + 0 * 64 + n0 + n];
                float Gf = ((n & 1) ? G[1][n >> 1].y : G[1][n >> 1].x)
                         + sm[OFF_CB2 + 1 * 64 + n0 + n];
                float Gg = ((n & 1) ? G[2][n >> 1].y : G[2][n >> 1].x)
                         + sm[OFF_CB2 + 2 * 64 + n0 + n];
                float Go = ((n & 1) ? G[3][n >> 1].y : G[3][n >> 1].x)
                         + sm[OFF_CB2 + 3 * 64 + n0 + n];
                float sp;
                cellpw(Gi, Gf, Gg, Go, syn2[n][j], mem2[n][j], sp, thr2);
                oa[j][0] += sp * sm[OFF_WOUT + wcol + n0 + n];
                oa[j][1] += sp * sm[OFF_WOUT + 1664 + wcol + n0 + n];
            }
        }
    }

    // ---- final mem2 contribution (columns 25*64 .. 25*64+63) ----
#pragma unroll
    for (int n = 0; n < 4; ++n) {
        float wm0 = sm[OFF_WOUT + 25 * 64 + n0 + n];
        float wm1 = sm[OFF_WOUT + 1664 + 25 * 64 + n0 + n];
#pragma unroll
        for (int j = 0; j < JB; ++j) {
            oa[j][0] += mem2[n][j] * wm0;
            oa[j][1] += mem2[n][j] * wm1;
        }
    }

    // ---- reduce over the 16 neuron-owner lanes of this half-warp ----
#pragma unroll
    for (int j = 0; j < JB; ++j)
#pragma unroll
        for (int k = 0; k < 2; ++k) {
            float v = oa[j][k];
#pragma unroll
            for (int off = 8; off; off >>= 1)
                v += __shfl_xor_sync(FULLMASK, v, off);
            oa[j][k] = v;
        }

    if (hl < 2 * JB) {
        int j = hl >> 1, k = hl & 1;
        out[(cta_b0 + bl + j) * 2 + k] = oa[j][k] + bout[k];
    }
}

extern "C" void kernel_launch(void* const* d_in, const int* in_sizes, int n_in,
                              void* d_out, int out_size) {
    const float* x    = (const float*)d_in[0];
    const float* Wih1 = (const float*)d_in[1];
    const float* Whh1 = (const float*)d_in[2];
    const float* bih1 = (const float*)d_in[3];
    const float* bhh1 = (const float*)d_in[4];
    const float* thr1 = (const float*)d_in[5];
    const float* Wih2 = (const float*)d_in[6];
    const float* Whh2 = (const float*)d_in[7];
    const float* bih2 = (const float*)d_in[8];
    const float* bhh2 = (const float*)d_in[9];
    const float* thr2 = (const float*)d_in[10];
    const float* Wout = (const float*)d_in[11];
    const float* bout = (const float*)d_in[12];
    float* out = (float*)d_out;

    int B = in_sizes[0] / 24;  // 65536

    cudaFuncSetAttribute(snn_kernel,
                         cudaFuncAttributeMaxDynamicSharedMemorySize,
                         SMEM_BYTES);

    snn_kernel<<<B / 64, NT, SMEM_BYTES>>>(
        x, Wih1, Whh1, bih1, bhh1, thr1,
        Wih2, Whh2, bih2, bhh2, thr2, Wout, bout, out);
}